// round 10
// baseline (speedup 1.0000x reference)
#include <cuda_runtime.h>
#include <cuda_fp16.h>
#include <math.h>
#include <stdint.h>

#define MB 16384   // rows (2N)
#define DD 2048
#define HH 2048
#define FF 128
#define KK 2048    // K of both big GEMMs

constexpr float INV_T = 1.0f / 0.07f;
constexpr float C_EX2 = 20.6099773964f;   // INV_T * log2(e)

// ---------------- scratch --------------------------------------------------
__device__ __half g_fhi [(size_t)MB * DD];
__device__ __half g_w1hi[(size_t)HH * DD];
__device__ __half g_w2hi[(size_t)FF * HH];
__device__ __half g_w2lo[(size_t)FF * HH];
__device__ __half g_hhi [(size_t)MB * HH];
__device__ __half g_zhi [(size_t)MB * FF];
__device__ float g_z  [(size_t)MB * FF];
__device__ float g_ps [2 * MB];
__device__ float g_pos[MB];

// ---------------- helpers ---------------------------------------------------
__device__ __forceinline__ uint32_t smem_u32(const void* p) {
    uint32_t a;
    asm("{ .reg .u64 t; cvta.to.shared.u64 t, %1; cvt.u32.u64 %0, t; }"
        : "=r"(a) : "l"(p));
    return a;
}
__device__ __forceinline__ void cp16(uint32_t s, const void* g) {
    asm volatile("cp.async.cg.shared.global [%0], [%1], 16;" :: "r"(s), "l"(g));
}
#define CP_COMMIT() asm volatile("cp.async.commit_group;")
#define CP_WAIT(n)  asm volatile("cp.async.wait_group %0;" :: "n"(n))

__device__ __forceinline__ void ldsm4(uint32_t* r, uint32_t a) {
    asm volatile("ldmatrix.sync.aligned.m8n8.x4.shared.b16 {%0,%1,%2,%3}, [%4];"
                 : "=r"(r[0]), "=r"(r[1]), "=r"(r[2]), "=r"(r[3]) : "r"(a));
}
__device__ __forceinline__ void mma_f16(float* c, const uint32_t* a,
                                        uint32_t b0, uint32_t b1) {
    asm volatile(
        "mma.sync.aligned.m16n8k16.row.col.f32.f16.f16.f32 "
        "{%0,%1,%2,%3}, {%4,%5,%6,%7}, {%8,%9}, {%0,%1,%2,%3};"
        : "+f"(c[0]), "+f"(c[1]), "+f"(c[2]), "+f"(c[3])
        : "r"(a[0]), "r"(a[1]), "r"(a[2]), "r"(a[3]), "r"(b0), "r"(b1));
}
__device__ __forceinline__ uint32_t pack2h(float a, float b) {
    __half2 t = __floats2half2_rn(a, b);
    return *reinterpret_cast<uint32_t*>(&t);
}
__device__ __forceinline__ float ex2f(float x) {
    float r;
    asm("ex2.approx.f32 %0, %1;" : "=f"(r) : "f"(x));
    return r;
}

// ---------------------------------------------------------------------------
// prep
// ---------------------------------------------------------------------------
__global__ void cvt_k(const float* __restrict__ X, __half* __restrict__ Hi, size_t n)
{
    size_t stride = (size_t)gridDim.x * blockDim.x * 4;
    for (size_t i = ((size_t)blockIdx.x * blockDim.x + threadIdx.x) * 4; i < n; i += stride) {
        float4 v = *(const float4*)(X + i);
        __half h[4] = {__float2half_rn(v.x), __float2half_rn(v.y),
                       __float2half_rn(v.z), __float2half_rn(v.w)};
        *(uint2*)(Hi + i) = *(uint2*)h;
    }
}
__global__ void tsplit_k(const float* __restrict__ W, __half* __restrict__ Thi,
                         __half* __restrict__ Tlo, int K, int N)
{
    __shared__ float t[32][33];
    int nx = blockIdx.x * 32, ky = blockIdx.y * 32;
    int tx = threadIdx.x, ty = threadIdx.y;   // 32 x 8
#pragma unroll
    for (int i = 0; i < 4; i++)
        t[ty + 8 * i][tx] = W[(size_t)(ky + ty + 8 * i) * N + nx + tx];
    __syncthreads();
#pragma unroll
    for (int i = 0; i < 4; i++) {
        float v = t[tx][ty + 8 * i];
        __half h = __float2half_rn(v);
        size_t o = (size_t)(nx + ty + 8 * i) * K + ky + tx;
        Thi[o] = h;
        if (Tlo) Tlo[o] = __float2half_rn(v - __half2float(h));
    }
}

// ---------------------------------------------------------------------------
// GEMM1: pure fp16. C = relu(A @ B^T + bias). 128x128, Kc=32, 6-stage.
// Warp-parity ks staggering: half the warps LDSM while half MMA.
// ---------------------------------------------------------------------------
__global__ __launch_bounds__(256, 2)
void hgemm1_k(const __half* __restrict__ Ahi, const __half* __restrict__ Bhi,
              const float* __restrict__ bias, int Nout, __half* __restrict__ Chi)
{
    extern __shared__ char smem[];
    const uint32_t sb = smem_u32(smem);
    const int tid = threadIdx.x;
    const int bx = blockIdx.x, by = blockIdx.y;
    const int lane = tid & 31, warp = tid >> 5;
    const int wm = warp & 1, wn = warp >> 1;
    const int quad = lane >> 3, l8 = lane & 7;
    const int wpar = warp & 1;   // phase stagger

    float* bias_s = (float*)(smem + 98304);
    if (tid < 128) bias_s[tid] = bias[bx * 128 + tid];

    const int lrow = tid >> 1, lhalf = tid & 1;
    const __half* gA0 = Ahi + (size_t)(by * 128 + lrow) * KK;
    const __half* gB0 = Bhi + (size_t)(bx * 128 + lrow) * KK;
    const uint32_t lso = (uint32_t)(lrow >> 3) * 512 + (lrow & 7) * 16;

    auto load_stage = [&](int kt) {
        uint32_t st = sb + (uint32_t)(kt % 6) * 16384;
        const int kbase = kt * 32;
#pragma unroll
        for (int j = 0; j < 2; j++) {
            int kb = lhalf * 2 + j;
            uint32_t so = lso + (uint32_t)kb * 128;
            cp16(st + so,         gA0 + kbase + kb * 8);
            cp16(st + 8192 + so,  gB0 + kbase + kb * 8);
        }
        CP_COMMIT();
    };

    float acc[4][4][4];
#pragma unroll
    for (int f = 0; f < 4; f++)
#pragma unroll
        for (int n = 0; n < 4; n++)
#pragma unroll
            for (int q = 0; q < 4; q++) acc[f][n][q] = 0.f;

    const uint32_t aoff = (uint32_t)(quad & 1) * 512 + (uint32_t)(quad >> 1) * 128 + l8 * 16;
    const uint32_t boff = (uint32_t)(quad >> 1) * 512 + (uint32_t)(quad & 1) * 128 + l8 * 16;

    const int NKT = KK / 32;   // 64
    load_stage(0); load_stage(1); load_stage(2); load_stage(3); load_stage(4);
    for (int kt = 0; kt < NKT; kt++) {
        CP_WAIT(4);
        __syncthreads();
        if (kt + 5 < NKT) load_stage(kt + 5);
        const uint32_t st = sb + (uint32_t)(kt % 6) * 16384;
#pragma unroll
        for (int kk = 0; kk < 2; kk++) {
            const int ks = kk ^ wpar;   // even warps: 0,1; odd warps: 1,0
            uint32_t ah[4][4], bh[2][4];
#pragma unroll
            for (int f = 0; f < 4; f++)
                ldsm4(ah[f], st + (uint32_t)(wm * 8 + f * 2) * 512 + ks * 256 + aoff);
#pragma unroll
            for (int p = 0; p < 2; p++)
                ldsm4(bh[p], st + 8192 + (uint32_t)(wn * 4 + p * 2) * 512 + ks * 256 + boff);
#pragma unroll
            for (int f = 0; f < 4; f++)
#pragma unroll
                for (int nf = 0; nf < 4; nf++) {
                    int p = nf >> 1, q = (nf & 1) * 2;
                    mma_f16(acc[f][nf], ah[f], bh[p][q], bh[p][q + 1]);
                }
        }
    }

    const int rsub = lane >> 2;
    const int csub = (lane & 3) * 2;
#pragma unroll
    for (int f = 0; f < 4; f++) {
        int r0 = by * 128 + wm * 64 + f * 16 + rsub;
#pragma unroll
        for (int nf = 0; nf < 4; nf++) {
            int cn = wn * 32 + nf * 8 + csub;
            float b0 = bias_s[cn], b1 = bias_s[cn + 1];
            float v00 = fmaxf(acc[f][nf][0] + b0, 0.f);
            float v01 = fmaxf(acc[f][nf][1] + b1, 0.f);
            float v10 = fmaxf(acc[f][nf][2] + b0, 0.f);
            float v11 = fmaxf(acc[f][nf][3] + b1, 0.f);
            size_t o0 = (size_t)r0 * Nout + bx * 128 + cn;
            size_t o1 = o0 + (size_t)8 * Nout;
            *(uint32_t*)(Chi + o0) = pack2h(v00, v01);
            *(uint32_t*)(Chi + o1) = pack2h(v10, v11);
        }
    }
}

// ---------------------------------------------------------------------------
// GEMM2: 64-row tiles. A fp16, B = w2 hi+lo, fused L2-normalize.
// Kc=32, 4-stage x 20KB, warp-parity staggering.
// ---------------------------------------------------------------------------
__global__ __launch_bounds__(256, 2)
void hgemm2_k(const __half* __restrict__ Ahi,
              const __half* __restrict__ Bhi, const __half* __restrict__ Blo,
              const float* __restrict__ bias,
              float* __restrict__ Zf, __half* __restrict__ Zhi,
              float* __restrict__ outz)
{
    extern __shared__ char smem[];
    const uint32_t sb = smem_u32(smem);
    const int tid = threadIdx.x;
    const int by = blockIdx.y;
    const int lane = tid & 31, warp = tid >> 5;
    const int wm = warp & 1, wn = warp >> 1;
    const int quad = lane >> 3, l8 = lane & 7;
    const int wpar = warp & 1;

    float* bias_s = (float*)(smem + 81920);
    float* rowsq4 = (float*)(smem + 81920 + 512);   // [4][64]
    if (tid < 128) bias_s[tid] = bias[tid];

    const int arow = tid >> 2, akb = tid & 3;
    const uint32_t aso = (uint32_t)(arow >> 3) * 512 + (arow & 7) * 16 + akb * 128;
    const __half* gA0 = Ahi + (size_t)(by * 64 + arow) * KK + akb * 8;
    const int lrow = tid >> 1, lhalf = tid & 1;
    const uint32_t lso = (uint32_t)(lrow >> 3) * 512 + (lrow & 7) * 16;
    const __half* gB0 = Bhi + (size_t)lrow * KK;
    const __half* gB1 = Blo + (size_t)lrow * KK;

    auto load_stage = [&](int kt) {
        uint32_t st = sb + (uint32_t)(kt & 3) * 20480;
        const int kbase = kt * 32;
        cp16(st + aso, gA0 + kbase);
#pragma unroll
        for (int j = 0; j < 2; j++) {
            int kb = lhalf * 2 + j;
            uint32_t so = lso + (uint32_t)kb * 128;
            cp16(st + 4096 + so,   gB0 + kbase + kb * 8);
            cp16(st + 12288 + so,  gB1 + kbase + kb * 8);
        }
        CP_COMMIT();
    };

    float acc[2][4][4];
#pragma unroll
    for (int f = 0; f < 2; f++)
#pragma unroll
        for (int n = 0; n < 4; n++)
#pragma unroll
            for (int q = 0; q < 4; q++) acc[f][n][q] = 0.f;

    const uint32_t aoff = (uint32_t)(quad & 1) * 512 + (uint32_t)(quad >> 1) * 128 + l8 * 16;
    const uint32_t boff = (uint32_t)(quad >> 1) * 512 + (uint32_t)(quad & 1) * 128 + l8 * 16;

    const int NKT = KK / 32;
    load_stage(0); load_stage(1); load_stage(2);
    for (int kt = 0; kt < NKT; kt++) {
        CP_WAIT(2);
        __syncthreads();
        if (kt + 3 < NKT) load_stage(kt + 3);
        const uint32_t st = sb + (uint32_t)(kt & 3) * 20480;
#pragma unroll
        for (int kk = 0; kk < 2; kk++) {
            const int ks = kk ^ wpar;
            uint32_t ah[2][4], bh[2][4], bl[2][4];
#pragma unroll
            for (int f = 0; f < 2; f++)
                ldsm4(ah[f], st + (uint32_t)(wm * 4 + f * 2) * 512 + ks * 256 + aoff);
#pragma unroll
            for (int p = 0; p < 2; p++) {
                uint32_t base = (uint32_t)(wn * 4 + p * 2) * 512 + ks * 256 + boff;
                ldsm4(bh[p], st + 4096 + base);
                ldsm4(bl[p], st + 12288 + base);
            }
#pragma unroll
            for (int f = 0; f < 2; f++)
#pragma unroll
                for (int nf = 0; nf < 4; nf++) {
                    int p = nf >> 1, q = (nf & 1) * 2;
                    mma_f16(acc[f][nf], ah[f], bh[p][q], bh[p][q + 1]);
                    mma_f16(acc[f][nf], ah[f], bl[p][q], bl[p][q + 1]);
                }
        }
    }

    const int rsub = lane >> 2;
    const int csub = (lane & 3) * 2;
#pragma unroll
    for (int f = 0; f < 2; f++) {
        float s0 = 0.f, s1 = 0.f;
#pragma unroll
        for (int nf = 0; nf < 4; nf++) {
            int cn = wn * 32 + nf * 8 + csub;
            float b0 = bias_s[cn], b1 = bias_s[cn + 1];
            float v00 = acc[f][nf][0] + b0, v01 = acc[f][nf][1] + b1;
            float v10 = acc[f][nf][2] + b0, v11 = acc[f][nf][3] + b1;
            s0 += v00 * v00 + v01 * v01;
            s1 += v10 * v10 + v11 * v11;
        }
        s0 += __shfl_xor_sync(0xffffffffu, s0, 1);
        s0 += __shfl_xor_sync(0xffffffffu, s0, 2);
        s1 += __shfl_xor_sync(0xffffffffu, s1, 1);
        s1 += __shfl_xor_sync(0xffffffffu, s1, 2);
        if ((lane & 3) == 0) {
            int lr = wm * 32 + f * 16 + rsub;
            rowsq4[wn * 64 + lr] = s0;
            rowsq4[wn * 64 + lr + 8] = s1;
        }
    }
    __syncthreads();
#pragma unroll
    for (int f = 0; f < 2; f++) {
        int lr0 = wm * 32 + f * 16 + rsub;
        float sq0 = rowsq4[lr0] + rowsq4[64 + lr0] + rowsq4[128 + lr0] + rowsq4[192 + lr0];
        float sq1 = rowsq4[lr0 + 8] + rowsq4[64 + lr0 + 8] + rowsq4[128 + lr0 + 8] + rowsq4[192 + lr0 + 8];
        float inv0 = rsqrtf(fmaxf(sq0, 1e-24f));
        float inv1 = rsqrtf(fmaxf(sq1, 1e-24f));
        int r0 = by * 64 + lr0;
#pragma unroll
        for (int nf = 0; nf < 4; nf++) {
            int cn = wn * 32 + nf * 8 + csub;
            float b0 = bias_s[cn], b1 = bias_s[cn + 1];
            float z00 = (acc[f][nf][0] + b0) * inv0, z01 = (acc[f][nf][1] + b1) * inv0;
            float z10 = (acc[f][nf][2] + b0) * inv1, z11 = (acc[f][nf][3] + b1) * inv1;
            size_t o0 = (size_t)r0 * FF + cn;
            size_t o1 = o0 + (size_t)8 * FF;
            *(float2*)(Zf + o0) = make_float2(z00, z01);
            *(float2*)(Zf + o1) = make_float2(z10, z11);
            if (outz) {
                outz[o0] = z00; outz[o0 + 1] = z01;
                outz[o1] = z10; outz[o1 + 1] = z11;
            }
            *(uint32_t*)(Zhi + o0) = pack2h(z00, z01);
            *(uint32_t*)(Zhi + o1) = pack2h(z10, z11);
        }
    }
}

// ---------------------------------------------------------------------------
// HMMA masked exp-sum: grid (2 col-splits, 128 row-blocks); MUFU exp.
// ks-rotation by warp id staggers LDSM vs MMA phases across warps.
// ---------------------------------------------------------------------------
__global__ __launch_bounds__(256, 2)
void lse_hmma_k(const __half* __restrict__ Zhi, float* __restrict__ ps)
{
    extern __shared__ char smem[];
    const uint32_t sb = smem_u32(smem);
    const int tid = threadIdx.x;
    const int split = blockIdx.x, by = blockIdx.y;
    const int lane = tid & 31, warp = tid >> 5;
    const int wm = warp & 1, wn = warp >> 1;
    const int quad = lane >> 3, l8 = lane & 7;

    float* lsum4 = (float*)(smem + 98304);

    const int lrow = tid >> 1, lhalf = tid & 1;
    const uint32_t lso = (uint32_t)(lrow >> 3) * 2048 + (lrow & 7) * 16;

    {
        const __half* ga = Zhi + (size_t)(by * 128 + lrow) * FF;
#pragma unroll
        for (int j = 0; j < 8; j++) {
            int kb = lhalf * 8 + j;
            cp16(sb + lso + kb * 128, ga + kb * 8);
        }
    }
    auto loadB = [&](int bxt, int s) {
        uint32_t st = sb + 32768 + (uint32_t)s * 32768;
        const __half* gb = Zhi + (size_t)(bxt * 128 + lrow) * FF;
#pragma unroll
        for (int j = 0; j < 8; j++) {
            int kb = lhalf * 8 + j;
            cp16(st + lso + kb * 128, gb + kb * 8);
        }
        CP_COMMIT();
    };
    const int bx0 = split * 64;
    loadB(bx0, 0);   // commits A too

    float rs[4][2];
#pragma unroll
    for (int f = 0; f < 4; f++) { rs[f][0] = 0.f; rs[f][1] = 0.f; }

    const uint32_t aoff = (uint32_t)(quad & 1) * 2048 + (uint32_t)(quad >> 1) * 128 + l8 * 16;
    const uint32_t boff = (uint32_t)(quad >> 1) * 2048 + (uint32_t)(quad & 1) * 128 + l8 * 16;
    const int rsub = lane >> 2;
    const int csub = (lane & 3) * 2;

    for (int i = 0; i < 64; i++) {
        const int bxt = bx0 + i;
        const int s = i & 1;
        CP_WAIT(0);
        __syncthreads();
        if (i < 63) loadB(bx0 + i + 1, s ^ 1);

        float acc[4][4][4];
#pragma unroll
        for (int f = 0; f < 4; f++)
#pragma unroll
            for (int n = 0; n < 4; n++)
#pragma unroll
                for (int q = 0; q < 4; q++) acc[f][n][q] = 0.f;

        const uint32_t stB = sb + 32768 + (uint32_t)s * 32768;
#pragma unroll
        for (int kk = 0; kk < 8; kk++) {
            const int ks = (kk + warp) & 7;   // rotate phase per warp
            uint32_t ah[4][4], bh[2][4];
#pragma unroll
            for (int f = 0; f < 4; f++)
                ldsm4(ah[f], sb + (uint32_t)(wm * 8 + f * 2) * 2048 + ks * 256 + aoff);
#pragma unroll
            for (int p = 0; p < 2; p++)
                ldsm4(bh[p], stB + (uint32_t)(wn * 4 + p * 2) * 2048 + ks * 256 + boff);
#pragma unroll
            for (int f = 0; f < 4; f++)
#pragma unroll
                for (int nf = 0; nf < 4; nf++) {
                    int p = nf >> 1, q = (nf & 1) * 2;
                    mma_f16(acc[f][nf], ah[f], bh[p][q], bh[p][q + 1]);
                }
        }

        const bool diag = (bxt == by);
#pragma unroll
        for (int f = 0; f < 4; f++) {
#pragma unroll
            for (int nf = 0; nf < 4; nf++) {
                float e00 = ex2f(fmaf(acc[f][nf][0], C_EX2, -C_EX2));
                float e01 = ex2f(fmaf(acc[f][nf][1], C_EX2, -C_EX2));
                float e10 = ex2f(fmaf(acc[f][nf][2], C_EX2, -C_EX2));
                float e11 = ex2f(fmaf(acc[f][nf][3], C_EX2, -C_EX2));
                if (diag) {
                    int lr = wm * 64 + f * 16 + rsub;
                    int lc = wn * 32 + nf * 8 + csub;
                    if (lr == lc)         e00 = 0.f;
                    if (lr == lc + 1)     e01 = 0.f;
                    if (lr + 8 == lc)     e10 = 0.f;
                    if (lr + 8 == lc + 1) e11 = 0.f;
                }
                rs[f][0] += e00 + e01;
                rs[f][1] += e10 + e11;
            }
        }
    }

#pragma unroll
    for (int f = 0; f < 4; f++) {
#pragma unroll
        for (int h = 0; h < 2; h++) {
            float v = rs[f][h];
            v += __shfl_xor_sync(0xffffffffu, v, 1);
            v += __shfl_xor_sync(0xffffffffu, v, 2);
            if ((lane & 3) == 0)
                lsum4[wn * 128 + wm * 64 + f * 16 + h * 8 + rsub] = v;
        }
    }
    __syncthreads();
    if (tid < 128) {
        float tot = lsum4[tid] + lsum4[128 + tid] + lsum4[256 + tid] + lsum4[384 + tid];
        ps[(size_t)split * MB + by * 128 + tid] = tot;
    }
}

// ---------------------------------------------------------------------------
__global__ void pos_k(const float* __restrict__ Z, float* __restrict__ pos)
{
    const int row = blockIdx.x;
    const int t = threadIdx.x;
    const int prow = (row + MB / 2) & (MB - 1);
    float s = Z[(size_t)row * FF + t] * Z[(size_t)prow * FF + t];
#pragma unroll
    for (int o = 16; o; o >>= 1) s += __shfl_xor_sync(0xffffffffu, s, o);
    __shared__ float ws[4];
    if ((t & 31) == 0) ws[t >> 5] = s;
    __syncthreads();
    if (t == 0) pos[row] = (ws[0] + ws[1] + ws[2] + ws[3]) * INV_T;
}

__global__ void loss_k(const float* __restrict__ ps, const float* __restrict__ pos,
                       float* __restrict__ out)
{
    __shared__ float sm[256];
    const int t = threadIdx.x;
    float s = 0.f;
    for (int i = t; i < MB; i += 256) {
        float tot = ps[i] + ps[MB + i];
        s += logf(tot) + INV_T - pos[i];
    }
    sm[t] = s;
    __syncthreads();
    for (int o = 128; o; o >>= 1) {
        if (t < o) sm[t] += sm[t + o];
        __syncthreads();
    }
    if (t == 0) out[0] = sm[0] * (1.0f / MB);
}

// ---------------------------------------------------------------------------
extern "C" void kernel_launch(void* const* d_in, const int* in_sizes, int n_in,
                              void* d_out, int out_size)
{
    const float* features = (const float*)d_in[0];
    const float* w1 = (const float*)d_in[1];
    const float* b1 = (const float*)d_in[2];
    const float* w2 = (const float*)d_in[3];
    const float* b2 = (const float*)d_in[4];
    float* out = (float*)d_out;

    __half *fhi, *w1hi, *w2hi, *w2lo, *hhi, *zhi;
    float *z, *psb, *posb;
    cudaGetSymbolAddress((void**)&fhi,  g_fhi);
    cudaGetSymbolAddress((void**)&w1hi, g_w1hi);
    cudaGetSymbolAddress((void**)&w2hi, g_w2hi);
    cudaGetSymbolAddress((void**)&w2lo, g_w2lo);
    cudaGetSymbolAddress((void**)&hhi,  g_hhi);
    cudaGetSymbolAddress((void**)&zhi,  g_zhi);
    cudaGetSymbolAddress((void**)&z,    g_z);
    cudaGetSymbolAddress((void**)&psb,  g_ps);
    cudaGetSymbolAddress((void**)&posb, g_pos);

    const int SM_G1 = 98304 + 512;           // 6 stages x 16KB + bias
    const int SM_G2 = 81920 + 512 + 1024;    // 4 stages x 20KB + bias + rowsq
    const int SM_L  = 98304 + 2048;          // A + 2 B stages + lsum
    cudaFuncSetAttribute(hgemm1_k,  cudaFuncAttributeMaxDynamicSharedMemorySize, SM_G1);
    cudaFuncSetAttribute(hgemm2_k,  cudaFuncAttributeMaxDynamicSharedMemorySize, SM_G2);
    cudaFuncSetAttribute(lse_hmma_k, cudaFuncAttributeMaxDynamicSharedMemorySize, SM_L);

    // prep
    cvt_k<<<1024, 256>>>(features, fhi, (size_t)MB * DD);
    tsplit_k<<<dim3(HH / 32, DD / 32), dim3(32, 8)>>>(w1, w1hi, nullptr, DD, HH);
    tsplit_k<<<dim3(FF / 32, HH / 32), dim3(32, 8)>>>(w2, w2hi, w2lo, HH, FF);

    // 1) h = relu(features @ w1 + b1)
    hgemm1_k<<<dim3(HH / 128, MB / 128), 256, SM_G1>>>(fhi, w1hi, b1, HH, hhi);

    // 2) p = h @ w2 + b2, fused L2-normalize
    float* outz = (out_size >= 1 + MB * FF) ? (out + 1) : nullptr;
    hgemm2_k<<<dim3(1, MB / 64), 256, SM_G2>>>(hhi, w2hi, w2lo, b2, z, zhi, outz);

    // 3) pos, 4) masked exp-sums, 5) loss
    pos_k<<<MB, 128>>>(z, posb);
    lse_hmma_k<<<dim3(2, MB / 128), 256, SM_L>>>(zhi, psb);
    loss_k<<<1, 256>>>(psb, posb, out);
}

// round 11
// speedup vs baseline: 1.1233x; 1.1233x over previous
#include <cuda_runtime.h>
#include <cuda_fp16.h>
#include <math.h>
#include <stdint.h>

#define MB 16384   // rows (2N)
#define DD 2048
#define HH 2048
#define FF 128
#define KK 2048    // K of both big GEMMs

constexpr float INV_T = 1.0f / 0.07f;
constexpr float C_EX2 = 20.6099773964f;   // INV_T * log2(e)

// ---------------- scratch --------------------------------------------------
__device__ __half g_fhi [(size_t)MB * DD];
__device__ __half g_w1hi[(size_t)HH * DD];
__device__ __half g_w2hi[(size_t)FF * HH];
__device__ __half g_w2lo[(size_t)FF * HH];
__device__ __half g_hhi [(size_t)MB * HH];
__device__ __half g_zhi [(size_t)MB * FF];
__device__ float g_z  [(size_t)MB * FF];
__device__ float g_ps [(size_t)128 * MB];   // 8MB: partial exp-sums [colblk][row]
__device__ float g_lse[MB];
__device__ float g_pos[MB];

// ---------------- helpers ---------------------------------------------------
__device__ __forceinline__ uint32_t smem_u32(const void* p) {
    uint32_t a;
    asm("{ .reg .u64 t; cvta.to.shared.u64 t, %1; cvt.u32.u64 %0, t; }"
        : "=r"(a) : "l"(p));
    return a;
}
__device__ __forceinline__ void cp16(uint32_t s, const void* g) {
    asm volatile("cp.async.cg.shared.global [%0], [%1], 16;" :: "r"(s), "l"(g));
}
#define CP_COMMIT() asm volatile("cp.async.commit_group;")
#define CP_WAIT(n)  asm volatile("cp.async.wait_group %0;" :: "n"(n))

__device__ __forceinline__ void ldsm4(uint32_t* r, uint32_t a) {
    asm volatile("ldmatrix.sync.aligned.m8n8.x4.shared.b16 {%0,%1,%2,%3}, [%4];"
                 : "=r"(r[0]), "=r"(r[1]), "=r"(r[2]), "=r"(r[3]) : "r"(a));
}
__device__ __forceinline__ void mma_f16(float* c, const uint32_t* a,
                                        uint32_t b0, uint32_t b1) {
    asm volatile(
        "mma.sync.aligned.m16n8k16.row.col.f32.f16.f16.f32 "
        "{%0,%1,%2,%3}, {%4,%5,%6,%7}, {%8,%9}, {%0,%1,%2,%3};"
        : "+f"(c[0]), "+f"(c[1]), "+f"(c[2]), "+f"(c[3])
        : "r"(a[0]), "r"(a[1]), "r"(a[2]), "r"(a[3]), "r"(b0), "r"(b1));
}
__device__ __forceinline__ uint32_t pack2h(float a, float b) {
    __half2 t = __floats2half2_rn(a, b);
    return *reinterpret_cast<uint32_t*>(&t);
}
__device__ __forceinline__ float ex2f(float x) {
    float r;
    asm("ex2.approx.f32 %0, %1;" : "=f"(r) : "f"(x));
    return r;
}

// ---------------------------------------------------------------------------
// prep
// ---------------------------------------------------------------------------
__global__ void cvt_k(const float* __restrict__ X, __half* __restrict__ Hi, size_t n)
{
    size_t stride = (size_t)gridDim.x * blockDim.x * 4;
    for (size_t i = ((size_t)blockIdx.x * blockDim.x + threadIdx.x) * 4; i < n; i += stride) {
        float4 v = *(const float4*)(X + i);
        __half h[4] = {__float2half_rn(v.x), __float2half_rn(v.y),
                       __float2half_rn(v.z), __float2half_rn(v.w)};
        *(uint2*)(Hi + i) = *(uint2*)h;
    }
}
__global__ void tsplit_k(const float* __restrict__ W, __half* __restrict__ Thi,
                         __half* __restrict__ Tlo, int K, int N)
{
    __shared__ float t[32][33];
    int nx = blockIdx.x * 32, ky = blockIdx.y * 32;
    int tx = threadIdx.x, ty = threadIdx.y;   // 32 x 8
#pragma unroll
    for (int i = 0; i < 4; i++)
        t[ty + 8 * i][tx] = W[(size_t)(ky + ty + 8 * i) * N + nx + tx];
    __syncthreads();
#pragma unroll
    for (int i = 0; i < 4; i++) {
        float v = t[tx][ty + 8 * i];
        __half h = __float2half_rn(v);
        size_t o = (size_t)(nx + ty + 8 * i) * K + ky + tx;
        Thi[o] = h;
        if (Tlo) Tlo[o] = __float2half_rn(v - __half2float(h));
    }
}

// ---------------------------------------------------------------------------
// GEMM1: pure fp16. C = relu(A @ B^T + bias). 128x128, Kc=32, 6-stage.
// ---------------------------------------------------------------------------
__global__ __launch_bounds__(256, 2)
void hgemm1_k(const __half* __restrict__ Ahi, const __half* __restrict__ Bhi,
              const float* __restrict__ bias, int Nout, __half* __restrict__ Chi)
{
    extern __shared__ char smem[];
    const uint32_t sb = smem_u32(smem);
    const int tid = threadIdx.x;
    const int bx = blockIdx.x, by = blockIdx.y;
    const int lane = tid & 31, warp = tid >> 5;
    const int wm = warp & 1, wn = warp >> 1;
    const int quad = lane >> 3, l8 = lane & 7;

    float* bias_s = (float*)(smem + 98304);
    if (tid < 128) bias_s[tid] = bias[bx * 128 + tid];

    const int lrow = tid >> 1, lhalf = tid & 1;
    const __half* gA0 = Ahi + (size_t)(by * 128 + lrow) * KK;
    const __half* gB0 = Bhi + (size_t)(bx * 128 + lrow) * KK;
    const uint32_t lso = (uint32_t)(lrow >> 3) * 512 + (lrow & 7) * 16;

    auto load_stage = [&](int kt) {
        uint32_t st = sb + (uint32_t)(kt % 6) * 16384;
        const int kbase = kt * 32;
#pragma unroll
        for (int j = 0; j < 2; j++) {
            int kb = lhalf * 2 + j;
            uint32_t so = lso + (uint32_t)kb * 128;
            cp16(st + so,         gA0 + kbase + kb * 8);
            cp16(st + 8192 + so,  gB0 + kbase + kb * 8);
        }
        CP_COMMIT();
    };

    float acc[4][4][4];
#pragma unroll
    for (int f = 0; f < 4; f++)
#pragma unroll
        for (int n = 0; n < 4; n++)
#pragma unroll
            for (int q = 0; q < 4; q++) acc[f][n][q] = 0.f;

    const uint32_t aoff = (uint32_t)(quad & 1) * 512 + (uint32_t)(quad >> 1) * 128 + l8 * 16;
    const uint32_t boff = (uint32_t)(quad >> 1) * 512 + (uint32_t)(quad & 1) * 128 + l8 * 16;

    const int NKT = KK / 32;   // 64
    load_stage(0); load_stage(1); load_stage(2); load_stage(3); load_stage(4);
    for (int kt = 0; kt < NKT; kt++) {
        CP_WAIT(4);
        __syncthreads();
        if (kt + 5 < NKT) load_stage(kt + 5);
        const uint32_t st = sb + (uint32_t)(kt % 6) * 16384;
#pragma unroll
        for (int ks = 0; ks < 2; ks++) {
            uint32_t ah[4][4], bh[2][4];
#pragma unroll
            for (int f = 0; f < 4; f++)
                ldsm4(ah[f], st + (uint32_t)(wm * 8 + f * 2) * 512 + ks * 256 + aoff);
#pragma unroll
            for (int p = 0; p < 2; p++)
                ldsm4(bh[p], st + 8192 + (uint32_t)(wn * 4 + p * 2) * 512 + ks * 256 + boff);
#pragma unroll
            for (int f = 0; f < 4; f++)
#pragma unroll
                for (int nf = 0; nf < 4; nf++) {
                    int p = nf >> 1, q = (nf & 1) * 2;
                    mma_f16(acc[f][nf], ah[f], bh[p][q], bh[p][q + 1]);
                }
        }
    }

    const int rsub = lane >> 2;
    const int csub = (lane & 3) * 2;
#pragma unroll
    for (int f = 0; f < 4; f++) {
        int r0 = by * 128 + wm * 64 + f * 16 + rsub;
#pragma unroll
        for (int nf = 0; nf < 4; nf++) {
            int cn = wn * 32 + nf * 8 + csub;
            float b0 = bias_s[cn], b1 = bias_s[cn + 1];
            float v00 = fmaxf(acc[f][nf][0] + b0, 0.f);
            float v01 = fmaxf(acc[f][nf][1] + b1, 0.f);
            float v10 = fmaxf(acc[f][nf][2] + b0, 0.f);
            float v11 = fmaxf(acc[f][nf][3] + b1, 0.f);
            size_t o0 = (size_t)r0 * Nout + bx * 128 + cn;
            size_t o1 = o0 + (size_t)8 * Nout;
            *(uint32_t*)(Chi + o0) = pack2h(v00, v01);
            *(uint32_t*)(Chi + o1) = pack2h(v10, v11);
        }
    }
}

// ---------------------------------------------------------------------------
// GEMM2: 64-row tiles. A fp16, B = w2 hi+lo, fused L2-normalize.
// ---------------------------------------------------------------------------
__global__ __launch_bounds__(256, 2)
void hgemm2_k(const __half* __restrict__ Ahi,
              const __half* __restrict__ Bhi, const __half* __restrict__ Blo,
              const float* __restrict__ bias,
              float* __restrict__ Zf, __half* __restrict__ Zhi,
              float* __restrict__ outz)
{
    extern __shared__ char smem[];
    const uint32_t sb = smem_u32(smem);
    const int tid = threadIdx.x;
    const int by = blockIdx.y;
    const int lane = tid & 31, warp = tid >> 5;
    const int wm = warp & 1, wn = warp >> 1;
    const int quad = lane >> 3, l8 = lane & 7;

    float* bias_s = (float*)(smem + 81920);
    float* rowsq4 = (float*)(smem + 81920 + 512);   // [4][64]
    if (tid < 128) bias_s[tid] = bias[tid];

    const int arow = tid >> 2, akb = tid & 3;
    const uint32_t aso = (uint32_t)(arow >> 3) * 512 + (arow & 7) * 16 + akb * 128;
    const __half* gA0 = Ahi + (size_t)(by * 64 + arow) * KK + akb * 8;
    const int lrow = tid >> 1, lhalf = tid & 1;
    const uint32_t lso = (uint32_t)(lrow >> 3) * 512 + (lrow & 7) * 16;
    const __half* gB0 = Bhi + (size_t)lrow * KK;
    const __half* gB1 = Blo + (size_t)lrow * KK;

    auto load_stage = [&](int kt) {
        uint32_t st = sb + (uint32_t)(kt & 3) * 20480;
        const int kbase = kt * 32;
        cp16(st + aso, gA0 + kbase);
#pragma unroll
        for (int j = 0; j < 2; j++) {
            int kb = lhalf * 2 + j;
            uint32_t so = lso + (uint32_t)kb * 128;
            cp16(st + 4096 + so,   gB0 + kbase + kb * 8);
            cp16(st + 12288 + so,  gB1 + kbase + kb * 8);
        }
        CP_COMMIT();
    };

    float acc[2][4][4];
#pragma unroll
    for (int f = 0; f < 2; f++)
#pragma unroll
        for (int n = 0; n < 4; n++)
#pragma unroll
            for (int q = 0; q < 4; q++) acc[f][n][q] = 0.f;

    const uint32_t aoff = (uint32_t)(quad & 1) * 512 + (uint32_t)(quad >> 1) * 128 + l8 * 16;
    const uint32_t boff = (uint32_t)(quad >> 1) * 512 + (uint32_t)(quad & 1) * 128 + l8 * 16;

    const int NKT = KK / 32;
    load_stage(0); load_stage(1); load_stage(2);
    for (int kt = 0; kt < NKT; kt++) {
        CP_WAIT(2);
        __syncthreads();
        if (kt + 3 < NKT) load_stage(kt + 3);
        const uint32_t st = sb + (uint32_t)(kt & 3) * 20480;
#pragma unroll
        for (int ks = 0; ks < 2; ks++) {
            uint32_t ah[2][4], bh[2][4], bl[2][4];
#pragma unroll
            for (int f = 0; f < 2; f++)
                ldsm4(ah[f], st + (uint32_t)(wm * 4 + f * 2) * 512 + ks * 256 + aoff);
#pragma unroll
            for (int p = 0; p < 2; p++) {
                uint32_t base = (uint32_t)(wn * 4 + p * 2) * 512 + ks * 256 + boff;
                ldsm4(bh[p], st + 4096 + base);
                ldsm4(bl[p], st + 12288 + base);
            }
#pragma unroll
            for (int f = 0; f < 2; f++)
#pragma unroll
                for (int nf = 0; nf < 4; nf++) {
                    int p = nf >> 1, q = (nf & 1) * 2;
                    mma_f16(acc[f][nf], ah[f], bh[p][q], bh[p][q + 1]);
                    mma_f16(acc[f][nf], ah[f], bl[p][q], bl[p][q + 1]);
                }
        }
    }

    const int rsub = lane >> 2;
    const int csub = (lane & 3) * 2;
#pragma unroll
    for (int f = 0; f < 2; f++) {
        float s0 = 0.f, s1 = 0.f;
#pragma unroll
        for (int nf = 0; nf < 4; nf++) {
            int cn = wn * 32 + nf * 8 + csub;
            float b0 = bias_s[cn], b1 = bias_s[cn + 1];
            float v00 = acc[f][nf][0] + b0, v01 = acc[f][nf][1] + b1;
            float v10 = acc[f][nf][2] + b0, v11 = acc[f][nf][3] + b1;
            s0 += v00 * v00 + v01 * v01;
            s1 += v10 * v10 + v11 * v11;
        }
        s0 += __shfl_xor_sync(0xffffffffu, s0, 1);
        s0 += __shfl_xor_sync(0xffffffffu, s0, 2);
        s1 += __shfl_xor_sync(0xffffffffu, s1, 1);
        s1 += __shfl_xor_sync(0xffffffffu, s1, 2);
        if ((lane & 3) == 0) {
            int lr = wm * 32 + f * 16 + rsub;
            rowsq4[wn * 64 + lr] = s0;
            rowsq4[wn * 64 + lr + 8] = s1;
        }
    }
    __syncthreads();
#pragma unroll
    for (int f = 0; f < 2; f++) {
        int lr0 = wm * 32 + f * 16 + rsub;
        float sq0 = rowsq4[lr0] + rowsq4[64 + lr0] + rowsq4[128 + lr0] + rowsq4[192 + lr0];
        float sq1 = rowsq4[lr0 + 8] + rowsq4[64 + lr0 + 8] + rowsq4[128 + lr0 + 8] + rowsq4[192 + lr0 + 8];
        float inv0 = rsqrtf(fmaxf(sq0, 1e-24f));
        float inv1 = rsqrtf(fmaxf(sq1, 1e-24f));
        int r0 = by * 64 + lr0;
#pragma unroll
        for (int nf = 0; nf < 4; nf++) {
            int cn = wn * 32 + nf * 8 + csub;
            float b0 = bias_s[cn], b1 = bias_s[cn + 1];
            float z00 = (acc[f][nf][0] + b0) * inv0, z01 = (acc[f][nf][1] + b1) * inv0;
            float z10 = (acc[f][nf][2] + b0) * inv1, z11 = (acc[f][nf][3] + b1) * inv1;
            size_t o0 = (size_t)r0 * FF + cn;
            size_t o1 = o0 + (size_t)8 * FF;
            *(float2*)(Zf + o0) = make_float2(z00, z01);
            *(float2*)(Zf + o1) = make_float2(z10, z11);
            if (outz) {   // d_out+1 only 4B aligned: scalar stores
                outz[o0] = z00; outz[o0 + 1] = z01;
                outz[o1] = z10; outz[o1 + 1] = z11;
            }
            *(uint32_t*)(Zhi + o0) = pack2h(z00, z01);
            *(uint32_t*)(Zhi + o1) = pack2h(z10, z11);
        }
    }
}

// ---------------------------------------------------------------------------
// Triangular lse tile kernel: one 128x128 sim tile per CTA, lower triangle
// only (8256 CTAs). Each tile contributes row-sums (block by) AND column-sums
// (block bx) -> ps[colblk][row], every slot written exactly once.
// smem: A 32KB | B 32KB | colarr 1KB | lsum 2KB. 2 CTAs/SM.
// ---------------------------------------------------------------------------
__global__ __launch_bounds__(256, 2)
void lse_tri_k(const __half* __restrict__ Zhi, float* __restrict__ ps)
{
    extern __shared__ char smem[];
    const uint32_t sb = smem_u32(smem);
    float* colarr = (float*)(smem + 65536);   // [2][128]
    float* lsum4  = (float*)(smem + 66560);   // [4][128]

    const int tid = threadIdx.x;
    const int lane = tid & 31, warp = tid >> 5;
    const int wm = warp & 1, wn = warp >> 1;
    const int quad = lane >> 3, l8 = lane & 7;

    // triangular decode: t -> (by, bx), bx <= by
    const int t = blockIdx.x;
    int by = (int)((sqrtf(8.0f * (float)t + 1.0f) - 1.0f) * 0.5f);
    while ((by + 1) * (by + 2) / 2 <= t) by++;
    while (by * (by + 1) / 2 > t) by--;
    const int bx = t - by * (by + 1) / 2;

    // load A (rows of by) and B (rows of bx)
    const int lrow = tid >> 1, lhalf = tid & 1;
    const uint32_t lso = (uint32_t)(lrow >> 3) * 2048 + (lrow & 7) * 16;
    {
        const __half* ga = Zhi + (size_t)(by * 128 + lrow) * FF;
        const __half* gb = Zhi + (size_t)(bx * 128 + lrow) * FF;
#pragma unroll
        for (int j = 0; j < 8; j++) {
            int kb = lhalf * 8 + j;
            cp16(sb + lso + kb * 128,         ga + kb * 8);
            cp16(sb + 32768 + lso + kb * 128, gb + kb * 8);
        }
        CP_COMMIT();
    }
    CP_WAIT(0);
    __syncthreads();

    float acc[4][4][4];
#pragma unroll
    for (int f = 0; f < 4; f++)
#pragma unroll
        for (int n = 0; n < 4; n++)
#pragma unroll
            for (int q = 0; q < 4; q++) acc[f][n][q] = 0.f;

    const uint32_t aoff = (uint32_t)(quad & 1) * 2048 + (uint32_t)(quad >> 1) * 128 + l8 * 16;
    const uint32_t boff = (uint32_t)(quad >> 1) * 2048 + (uint32_t)(quad & 1) * 128 + l8 * 16;

#pragma unroll
    for (int ks = 0; ks < 8; ks++) {
        uint32_t ah[4][4], bh[2][4];
#pragma unroll
        for (int f = 0; f < 4; f++)
            ldsm4(ah[f], sb + (uint32_t)(wm * 8 + f * 2) * 2048 + ks * 256 + aoff);
#pragma unroll
        for (int p = 0; p < 2; p++)
            ldsm4(bh[p], sb + 32768 + (uint32_t)(wn * 4 + p * 2) * 2048 + ks * 256 + boff);
#pragma unroll
        for (int f = 0; f < 4; f++)
#pragma unroll
            for (int nf = 0; nf < 4; nf++) {
                int p = nf >> 1, q = (nf & 1) * 2;
                mma_f16(acc[f][nf], ah[f], bh[p][q], bh[p][q + 1]);
            }
    }

    const int rsub = lane >> 2;
    const int csub = (lane & 3) * 2;
    const bool diag = (by == bx);

    float rs[4][2];       // row sums (block by)
    float colp[4][2];     // column partials (block bx)
#pragma unroll
    for (int f = 0; f < 4; f++) { rs[f][0] = 0.f; rs[f][1] = 0.f; }
#pragma unroll
    for (int nf = 0; nf < 4; nf++) { colp[nf][0] = 0.f; colp[nf][1] = 0.f; }

#pragma unroll
    for (int f = 0; f < 4; f++) {
#pragma unroll
        for (int nf = 0; nf < 4; nf++) {
            float e00 = ex2f(fmaf(acc[f][nf][0], C_EX2, -C_EX2));
            float e01 = ex2f(fmaf(acc[f][nf][1], C_EX2, -C_EX2));
            float e10 = ex2f(fmaf(acc[f][nf][2], C_EX2, -C_EX2));
            float e11 = ex2f(fmaf(acc[f][nf][3], C_EX2, -C_EX2));
            if (diag) {
                int lr = wm * 64 + f * 16 + rsub;
                int lc = wn * 32 + nf * 8 + csub;
                if (lr == lc)         e00 = 0.f;
                if (lr == lc + 1)     e01 = 0.f;
                if (lr + 8 == lc)     e10 = 0.f;
                if (lr + 8 == lc + 1) e11 = 0.f;
            }
            rs[f][0] += e00 + e01;
            rs[f][1] += e10 + e11;
            colp[nf][0] += e00 + e10;
            colp[nf][1] += e01 + e11;
        }
    }

    // ---- row-sum reduction (quad lanes -> per-wn slot -> sum of 4) ----
#pragma unroll
    for (int f = 0; f < 4; f++) {
#pragma unroll
        for (int h = 0; h < 2; h++) {
            float v = rs[f][h];
            v += __shfl_xor_sync(0xffffffffu, v, 1);
            v += __shfl_xor_sync(0xffffffffu, v, 2);
            if ((lane & 3) == 0)
                lsum4[wn * 128 + wm * 64 + f * 16 + h * 8 + rsub] = v;
        }
    }
    // ---- column-sum reduction (rsub lanes -> per-wm slot -> sum of 2) ----
#pragma unroll
    for (int nf = 0; nf < 4; nf++) {
#pragma unroll
        for (int h = 0; h < 2; h++) {
            float v = colp[nf][h];
            v += __shfl_xor_sync(0xffffffffu, v, 4);
            v += __shfl_xor_sync(0xffffffffu, v, 8);
            v += __shfl_xor_sync(0xffffffffu, v, 16);
            if (lane < 4)
                colarr[wm * 128 + wn * 32 + nf * 8 + lane * 2 + h] = v;
        }
    }
    __syncthreads();
    if (tid < 128) {
        float rtot = lsum4[tid] + lsum4[128 + tid] + lsum4[256 + tid] + lsum4[384 + tid];
        ps[(size_t)bx * MB + by * 128 + tid] = rtot;      // rows of by, colblk bx
        if (!diag) {
            float ctot = colarr[tid] + colarr[128 + tid];
            ps[(size_t)by * MB + bx * 128 + tid] = ctot;  // rows of bx, colblk by
        }
    }
}

// ---------------------------------------------------------------------------
// Sum 128 partials per row -> lse
// ---------------------------------------------------------------------------
__global__ void sumps_k(const float* __restrict__ ps, float* __restrict__ lse)
{
    const int row = blockIdx.x * 256 + threadIdx.x;
    float tot = 0.f;
#pragma unroll 8
    for (int c = 0; c < 128; c++) tot += ps[(size_t)c * MB + row];
    lse[row] = logf(tot) + INV_T;
}

// ---------------------------------------------------------------------------
__global__ void pos_k(const float* __restrict__ Z, float* __restrict__ pos)
{
    const int row = blockIdx.x;
    const int t = threadIdx.x;
    const int prow = (row + MB / 2) & (MB - 1);
    float s = Z[(size_t)row * FF + t] * Z[(size_t)prow * FF + t];
#pragma unroll
    for (int o = 16; o; o >>= 1) s += __shfl_xor_sync(0xffffffffu, s, o);
    __shared__ float ws[4];
    if ((t & 31) == 0) ws[t >> 5] = s;
    __syncthreads();
    if (t == 0) pos[row] = (ws[0] + ws[1] + ws[2] + ws[3]) * INV_T;
}

__global__ void loss_k(const float* __restrict__ lse, const float* __restrict__ pos,
                       float* __restrict__ out)
{
    __shared__ float sm[256];
    const int t = threadIdx.x;
    float s = 0.f;
    for (int i = t; i < MB; i += 256) s += lse[i] - pos[i];
    sm[t] = s;
    __syncthreads();
    for (int o = 128; o; o >>= 1) {
        if (t < o) sm[t] += sm[t + o];
        __syncthreads();
    }
    if (t == 0) out[0] = sm[0] * (1.0f / MB);
}

// ---------------------------------------------------------------------------
extern "C" void kernel_launch(void* const* d_in, const int* in_sizes, int n_in,
                              void* d_out, int out_size)
{
    const float* features = (const float*)d_in[0];
    const float* w1 = (const float*)d_in[1];
    const float* b1 = (const float*)d_in[2];
    const float* w2 = (const float*)d_in[3];
    const float* b2 = (const float*)d_in[4];
    float* out = (float*)d_out;

    __half *fhi, *w1hi, *w2hi, *w2lo, *hhi, *zhi;
    float *z, *psb, *lseb, *posb;
    cudaGetSymbolAddress((void**)&fhi,  g_fhi);
    cudaGetSymbolAddress((void**)&w1hi, g_w1hi);
    cudaGetSymbolAddress((void**)&w2hi, g_w2hi);
    cudaGetSymbolAddress((void**)&w2lo, g_w2lo);
    cudaGetSymbolAddress((void**)&hhi,  g_hhi);
    cudaGetSymbolAddress((void**)&zhi,  g_zhi);
    cudaGetSymbolAddress((void**)&z,    g_z);
    cudaGetSymbolAddress((void**)&psb,  g_ps);
    cudaGetSymbolAddress((void**)&lseb, g_lse);
    cudaGetSymbolAddress((void**)&posb, g_pos);

    const int SM_G1 = 98304 + 512;           // 6 stages x 16KB + bias
    const int SM_G2 = 81920 + 512 + 1024;    // 4 stages x 20KB + bias + rowsq
    const int SM_L  = 65536 + 1024 + 2048;   // A + B + colarr + lsum
    cudaFuncSetAttribute(hgemm1_k, cudaFuncAttributeMaxDynamicSharedMemorySize, SM_G1);
    cudaFuncSetAttribute(hgemm2_k, cudaFuncAttributeMaxDynamicSharedMemorySize, SM_G2);
    cudaFuncSetAttribute(lse_tri_k, cudaFuncAttributeMaxDynamicSharedMemorySize, SM_L);

    // prep
    cvt_k<<<1024, 256>>>(features, fhi, (size_t)MB * DD);
    tsplit_k<<<dim3(HH / 32, DD / 32), dim3(32, 8)>>>(w1, w1hi, nullptr, DD, HH);
    tsplit_k<<<dim3(FF / 32, HH / 32), dim3(32, 8)>>>(w2, w2hi, w2lo, HH, FF);

    // 1) h = relu(features @ w1 + b1)
    hgemm1_k<<<dim3(HH / 128, MB / 128), 256, SM_G1>>>(fhi, w1hi, b1, HH, hhi);

    // 2) p = h @ w2 + b2, fused L2-normalize
    float* outz = (out_size >= 1 + MB * FF) ? (out + 1) : nullptr;
    hgemm2_k<<<dim3(1, MB / 64), 256, SM_G2>>>(hhi, w2hi, w2lo, b2, z, zhi, outz);

    // 3) pos
    pos_k<<<MB, 128>>>(z, posb);

    // 4) triangular masked exp-sum tiles (symmetry: half the MMAs)
    const int NTRI = (MB / 128) * (MB / 128 + 1) / 2;   // 8256
    lse_tri_k<<<NTRI, 256, SM_L>>>(zhi, psb);

    // 5) combine partials -> lse, 6) loss
    sumps_k<<<MB / 256, 256>>>(psb, lseb);
    loss_k<<<1, 256>>>(lseb, posb, out);
}

// round 13
// speedup vs baseline: 1.1341x; 1.0096x over previous
#include <cuda_runtime.h>
#include <cuda_fp16.h>
#include <math.h>
#include <stdint.h>

#define MB 16384   // rows (2N)
#define DD 2048
#define HH 2048
#define FF 128
#define KK 2048    // K of both big GEMMs

constexpr float INV_T = 1.0f / 0.07f;
constexpr float C_EX2 = 20.6099773964f;   // INV_T * log2(e)

// ---------------- scratch --------------------------------------------------
__device__ __half g_fhi [(size_t)MB * DD];
__device__ __half g_w1hi[(size_t)HH * DD];
__device__ __half g_w2hi[(size_t)FF * HH];
__device__ __half g_hhi [(size_t)MB * HH];
__device__ __half g_zhi [(size_t)MB * FF];
__device__ float g_z  [(size_t)MB * FF];
__device__ float g_ps [(size_t)128 * MB];   // 8MB partial exp-sums [colblk][row]
__device__ float g_lse[MB];
__device__ float g_pos[MB];

// ---------------- helpers ---------------------------------------------------
__device__ __forceinline__ uint32_t smem_u32(const void* p) {
    uint32_t a;
    asm("{ .reg .u64 t; cvta.to.shared.u64 t, %1; cvt.u32.u64 %0, t; }"
        : "=r"(a) : "l"(p));
    return a;
}
__device__ __forceinline__ void cp16(uint32_t s, const void* g) {
    asm volatile("cp.async.cg.shared.global [%0], [%1], 16;" :: "r"(s), "l"(g));
}
#define CP_COMMIT() asm volatile("cp.async.commit_group;")
#define CP_WAIT(n)  asm volatile("cp.async.wait_group %0;" :: "n"(n))

__device__ __forceinline__ void ldsm4(uint32_t* r, uint32_t a) {
    asm volatile("ldmatrix.sync.aligned.m8n8.x4.shared.b16 {%0,%1,%2,%3}, [%4];"
                 : "=r"(r[0]), "=r"(r[1]), "=r"(r[2]), "=r"(r[3]) : "r"(a));
}
__device__ __forceinline__ void mma_f16(float* c, const uint32_t* a,
                                        uint32_t b0, uint32_t b1) {
    asm volatile(
        "mma.sync.aligned.m16n8k16.row.col.f32.f16.f16.f32 "
        "{%0,%1,%2,%3}, {%4,%5,%6,%7}, {%8,%9}, {%0,%1,%2,%3};"
        : "+f"(c[0]), "+f"(c[1]), "+f"(c[2]), "+f"(c[3])
        : "r"(a[0]), "r"(a[1]), "r"(a[2]), "r"(a[3]), "r"(b0), "r"(b1));
}
__device__ __forceinline__ uint32_t pack2h(float a, float b) {
    __half2 t = __floats2half2_rn(a, b);
    return *reinterpret_cast<uint32_t*>(&t);
}
__device__ __forceinline__ float ex2f(float x) {
    float r;
    asm("ex2.approx.f32 %0, %1;" : "=f"(r) : "f"(x));
    return r;
}

// ---------------------------------------------------------------------------
// prep: fp32 -> fp16 convert (features); fused transpose for w1 AND w2
// ---------------------------------------------------------------------------
__global__ void cvt_k(const float* __restrict__ X, __half* __restrict__ Hi, size_t n)
{
    size_t stride = (size_t)gridDim.x * blockDim.x * 4;
    for (size_t i = ((size_t)blockIdx.x * blockDim.x + threadIdx.x) * 4; i < n; i += stride) {
        float4 v = *(const float4*)(X + i);
        __half h[4] = {__float2half_rn(v.x), __float2half_rn(v.y),
                       __float2half_rn(v.z), __float2half_rn(v.w)};
        *(uint2*)(Hi + i) = *(uint2*)h;
    }
}
// blockIdx.x < 64: w1 [2048 x 2048]; else w2 [2048 x 128]
__global__ void tprep_k(const float* __restrict__ W1, const float* __restrict__ W2,
                        __half* __restrict__ T1, __half* __restrict__ T2)
{
    __shared__ float t[32][33];
    const int bxr = blockIdx.x;
    const float* W;
    __half* T;
    int N, nxb;
    if (bxr < 64) { W = W1; T = T1; N = HH; nxb = bxr; }
    else          { W = W2; T = T2; N = FF; nxb = bxr - 64; }
    const int nx = nxb * 32, ky = blockIdx.y * 32;
    const int tx = threadIdx.x, ty = threadIdx.y;   // 32 x 8
#pragma unroll
    for (int i = 0; i < 4; i++)
        t[ty + 8 * i][tx] = W[(size_t)(ky + ty + 8 * i) * N + nx + tx];
    __syncthreads();
#pragma unroll
    for (int i = 0; i < 4; i++) {
        float v = t[tx][ty + 8 * i];
        T[(size_t)(nx + ty + 8 * i) * KK + ky + tx] = __float2half_rn(v);
    }
}

// ---------------------------------------------------------------------------
// GEMM1: pure fp16. C = relu(A @ B^T + bias). 128x128, Kc=64, 3-stage,
// one sync/iter. UNIFORM group accounting: every iteration commits exactly
// one group (empty at the tail) so CP_WAIT(1) always completes the buffer
// about to be read — fixes the R12 tail race.
// ---------------------------------------------------------------------------
__global__ __launch_bounds__(256, 2)
void hgemm1_k(const __half* __restrict__ Ahi, const __half* __restrict__ Bhi,
              const float* __restrict__ bias, int Nout, __half* __restrict__ Chi)
{
    extern __shared__ char smem[];
    const uint32_t sb = smem_u32(smem);
    const int tid = threadIdx.x;
    const int bx = blockIdx.x, by = blockIdx.y;
    const int lane = tid & 31, warp = tid >> 5;
    const int wm = warp & 1, wn = warp >> 1;
    const int quad = lane >> 3, l8 = lane & 7;

    float* bias_s = (float*)(smem + 98304);
    if (tid < 128) bias_s[tid] = bias[bx * 128 + tid];

    const int lrow = tid >> 1, lhalf = tid & 1;
    const __half* gA0 = Ahi + (size_t)(by * 128 + lrow) * KK;
    const __half* gB0 = Bhi + (size_t)(bx * 128 + lrow) * KK;
    const uint32_t lso = (uint32_t)(lrow >> 3) * 1024 + (lrow & 7) * 16;

    auto load_stage = [&](int kt) {
        uint32_t st = sb + (uint32_t)(kt % 3) * 32768;
        const int kbase = kt * 64;
#pragma unroll
        for (int j = 0; j < 4; j++) {
            int kb = lhalf * 4 + j;
            uint32_t so = lso + (uint32_t)kb * 128;
            cp16(st + so,          gA0 + kbase + kb * 8);
            cp16(st + 16384 + so,  gB0 + kbase + kb * 8);
        }
        CP_COMMIT();
    };

    float acc[4][4][4];
#pragma unroll
    for (int f = 0; f < 4; f++)
#pragma unroll
        for (int n = 0; n < 4; n++)
#pragma unroll
            for (int q = 0; q < 4; q++) acc[f][n][q] = 0.f;

    const uint32_t aoff = (uint32_t)(quad & 1) * 1024 + (uint32_t)(quad >> 1) * 128 + l8 * 16;
    const uint32_t boff = (uint32_t)(quad >> 1) * 1024 + (uint32_t)(quad & 1) * 128 + l8 * 16;

    const int NKT = KK / 64;   // 32
    load_stage(0);
    load_stage(1);
    for (int kt = 0; kt < NKT; kt++) {
        // before this iteration's commit, the only allowed-pending group is the
        // one committed at kt-1 -> everything older (incl. buffer kt) complete.
        CP_WAIT(1);
        __syncthreads();
        if (kt + 2 < NKT) load_stage(kt + 2);
        else              CP_COMMIT();          // keep accounting uniform
        const uint32_t st = sb + (uint32_t)(kt % 3) * 32768;
#pragma unroll
        for (int ks = 0; ks < 4; ks++) {
            uint32_t ah[4][4], bh[2][4];
#pragma unroll
            for (int f = 0; f < 4; f++)
                ldsm4(ah[f], st + (uint32_t)(wm * 8 + f * 2) * 1024 + ks * 256 + aoff);
#pragma unroll
            for (int p = 0; p < 2; p++)
                ldsm4(bh[p], st + 16384 + (uint32_t)(wn * 4 + p * 2) * 1024 + ks * 256 + boff);
#pragma unroll
            for (int f = 0; f < 4; f++)
#pragma unroll
                for (int nf = 0; nf < 4; nf++) {
                    int p = nf >> 1, q = (nf & 1) * 2;
                    mma_f16(acc[f][nf], ah[f], bh[p][q], bh[p][q + 1]);
                }
        }
    }

    const int rsub = lane >> 2;
    const int csub = (lane & 3) * 2;
#pragma unroll
    for (int f = 0; f < 4; f++) {
        int r0 = by * 128 + wm * 64 + f * 16 + rsub;
#pragma unroll
        for (int nf = 0; nf < 4; nf++) {
            int cn = wn * 32 + nf * 8 + csub;
            float b0 = bias_s[cn], b1 = bias_s[cn + 1];
            float v00 = fmaxf(acc[f][nf][0] + b0, 0.f);
            float v01 = fmaxf(acc[f][nf][1] + b1, 0.f);
            float v10 = fmaxf(acc[f][nf][2] + b0, 0.f);
            float v11 = fmaxf(acc[f][nf][3] + b1, 0.f);
            size_t o0 = (size_t)r0 * Nout + bx * 128 + cn;
            size_t o1 = o0 + (size_t)8 * Nout;
            *(uint32_t*)(Chi + o0) = pack2h(v00, v01);
            *(uint32_t*)(Chi + o1) = pack2h(v10, v11);
        }
    }
}

// ---------------------------------------------------------------------------
// GEMM2: 64-row tiles, single-term fp16, fused L2-normalize.
// Kc=32, 4-stage x 12KB, uniform commits (tail race fixed).
// ---------------------------------------------------------------------------
__global__ __launch_bounds__(256, 2)
void hgemm2_k(const __half* __restrict__ Ahi, const __half* __restrict__ Bhi,
              const float* __restrict__ bias,
              float* __restrict__ Zf, __half* __restrict__ Zhi,
              float* __restrict__ outz)
{
    extern __shared__ char smem[];
    const uint32_t sb = smem_u32(smem);
    const int tid = threadIdx.x;
    const int by = blockIdx.y;
    const int lane = tid & 31, warp = tid >> 5;
    const int wm = warp & 1, wn = warp >> 1;
    const int quad = lane >> 3, l8 = lane & 7;

    float* bias_s = (float*)(smem + 49152);
    float* rowsq4 = (float*)(smem + 49152 + 512);   // [4][64]
    if (tid < 128) bias_s[tid] = bias[tid];

    const int arow = tid >> 2, akb = tid & 3;
    const uint32_t aso = (uint32_t)(arow >> 3) * 512 + (arow & 7) * 16 + akb * 128;
    const __half* gA0 = Ahi + (size_t)(by * 64 + arow) * KK + akb * 8;
    const int lrow = tid >> 1, lhalf = tid & 1;
    const uint32_t lso = (uint32_t)(lrow >> 3) * 512 + (lrow & 7) * 16;
    const __half* gB0 = Bhi + (size_t)lrow * KK;

    auto load_stage = [&](int kt) {
        uint32_t st = sb + (uint32_t)(kt & 3) * 12288;
        const int kbase = kt * 32;
        cp16(st + aso, gA0 + kbase);
#pragma unroll
        for (int j = 0; j < 2; j++) {
            int kb = lhalf * 2 + j;
            cp16(st + 4096 + lso + (uint32_t)kb * 128, gB0 + kbase + kb * 8);
        }
        CP_COMMIT();
    };

    float acc[2][4][4];
#pragma unroll
    for (int f = 0; f < 2; f++)
#pragma unroll
        for (int n = 0; n < 4; n++)
#pragma unroll
            for (int q = 0; q < 4; q++) acc[f][n][q] = 0.f;

    const uint32_t aoff = (uint32_t)(quad & 1) * 512 + (uint32_t)(quad >> 1) * 128 + l8 * 16;
    const uint32_t boff = (uint32_t)(quad >> 1) * 512 + (uint32_t)(quad & 1) * 128 + l8 * 16;

    const int NKT = KK / 32;
    load_stage(0); load_stage(1); load_stage(2);
    for (int kt = 0; kt < NKT; kt++) {
        CP_WAIT(2);
        __syncthreads();
        if (kt + 3 < NKT) load_stage(kt + 3);
        else              CP_COMMIT();          // uniform accounting
        const uint32_t st = sb + (uint32_t)(kt & 3) * 12288;
#pragma unroll
        for (int ks = 0; ks < 2; ks++) {
            uint32_t ah[2][4], bh[2][4];
#pragma unroll
            for (int f = 0; f < 2; f++)
                ldsm4(ah[f], st + (uint32_t)(wm * 4 + f * 2) * 512 + ks * 256 + aoff);
#pragma unroll
            for (int p = 0; p < 2; p++)
                ldsm4(bh[p], st + 4096 + (uint32_t)(wn * 4 + p * 2) * 512 + ks * 256 + boff);
#pragma unroll
            for (int f = 0; f < 2; f++)
#pragma unroll
                for (int nf = 0; nf < 4; nf++) {
                    int p = nf >> 1, q = (nf & 1) * 2;
                    mma_f16(acc[f][nf], ah[f], bh[p][q], bh[p][q + 1]);
                }
        }
    }

    const int rsub = lane >> 2;
    const int csub = (lane & 3) * 2;
#pragma unroll
    for (int f = 0; f < 2; f++) {
        float s0 = 0.f, s1 = 0.f;
#pragma unroll
        for (int nf = 0; nf < 4; nf++) {
            int cn = wn * 32 + nf * 8 + csub;
            float b0 = bias_s[cn], b1 = bias_s[cn + 1];
            float v00 = acc[f][nf][0] + b0, v01 = acc[f][nf][1] + b1;
            float v10 = acc[f][nf][2] + b0, v11 = acc[f][nf][3] + b1;
            s0 += v00 * v00 + v01 * v01;
            s1 += v10 * v10 + v11 * v11;
        }
        s0 += __shfl_xor_sync(0xffffffffu, s0, 1);
        s0 += __shfl_xor_sync(0xffffffffu, s0, 2);
        s1 += __shfl_xor_sync(0xffffffffu, s1, 1);
        s1 += __shfl_xor_sync(0xffffffffu, s1, 2);
        if ((lane & 3) == 0) {
            int lr = wm * 32 + f * 16 + rsub;
            rowsq4[wn * 64 + lr] = s0;
            rowsq4[wn * 64 + lr + 8] = s1;
        }
    }
    __syncthreads();
#pragma unroll
    for (int f = 0; f < 2; f++) {
        int lr0 = wm * 32 + f * 16 + rsub;
        float sq0 = rowsq4[lr0] + rowsq4[64 + lr0] + rowsq4[128 + lr0] + rowsq4[192 + lr0];
        float sq1 = rowsq4[lr0 + 8] + rowsq4[64 + lr0 + 8] + rowsq4[128 + lr0 + 8] + rowsq4[192 + lr0 + 8];
        float inv0 = rsqrtf(fmaxf(sq0, 1e-24f));
        float inv1 = rsqrtf(fmaxf(sq1, 1e-24f));
        int r0 = by * 64 + lr0;
#pragma unroll
        for (int nf = 0; nf < 4; nf++) {
            int cn = wn * 32 + nf * 8 + csub;
            float b0 = bias_s[cn], b1 = bias_s[cn + 1];
            float z00 = (acc[f][nf][0] + b0) * inv0, z01 = (acc[f][nf][1] + b1) * inv0;
            float z10 = (acc[f][nf][2] + b0) * inv1, z11 = (acc[f][nf][3] + b1) * inv1;
            size_t o0 = (size_t)r0 * FF + cn;
            size_t o1 = o0 + (size_t)8 * FF;
            *(float2*)(Zf + o0) = make_float2(z00, z01);
            *(float2*)(Zf + o1) = make_float2(z10, z11);
            if (outz) {   // d_out+1 only 4B aligned: scalar stores
                outz[o0] = z00; outz[o0 + 1] = z01;
                outz[o1] = z10; outz[o1 + 1] = z11;
            }
            *(uint32_t*)(Zhi + o0) = pack2h(z00, z01);
            *(uint32_t*)(Zhi + o1) = pack2h(z10, z11);
        }
    }
}

// ---------------------------------------------------------------------------
// Triangular lse tile kernel (lower triangle, 8256 CTAs): row-sums for by,
// column-sums for bx -> ps[colblk][row]; every slot written exactly once.
// Single load, CP_WAIT(0) -> no pipeline race possible.
// ---------------------------------------------------------------------------
__global__ __launch_bounds__(256, 2)
void lse_tri_k(const __half* __restrict__ Zhi, float* __restrict__ ps)
{
    extern __shared__ char smem[];
    const uint32_t sb = smem_u32(smem);
    float* colarr = (float*)(smem + 65536);   // [2][128]
    float* lsum4  = (float*)(smem + 66560);   // [4][128]

    const int tid = threadIdx.x;
    const int lane = tid & 31, warp = tid >> 5;
    const int wm = warp & 1, wn = warp >> 1;
    const int quad = lane >> 3, l8 = lane & 7;

    const int t = blockIdx.x;
    int by = (int)((sqrtf(8.0f * (float)t + 1.0f) - 1.0f) * 0.5f);
    while ((by + 1) * (by + 2) / 2 <= t) by++;
    while (by * (by + 1) / 2 > t) by--;
    const int bx = t - by * (by + 1) / 2;

    const int lrow = tid >> 1, lhalf = tid & 1;
    const uint32_t lso = (uint32_t)(lrow >> 3) * 2048 + (lrow & 7) * 16;
    {
        const __half* ga = Zhi + (size_t)(by * 128 + lrow) * FF;
        const __half* gb = Zhi + (size_t)(bx * 128 + lrow) * FF;
#pragma unroll
        for (int j = 0; j < 8; j++) {
            int kb = lhalf * 8 + j;
            cp16(sb + lso + kb * 128,         ga + kb * 8);
            cp16(sb + 32768 + lso + kb * 128, gb + kb * 8);
        }
        CP_COMMIT();
    }
    CP_WAIT(0);
    __syncthreads();

    float acc[4][4][4];
#pragma unroll
    for (int f = 0; f < 4; f++)
#pragma unroll
        for (int n = 0; n < 4; n++)
#pragma unroll
            for (int q = 0; q < 4; q++) acc[f][n][q] = 0.f;

    const uint32_t aoff = (uint32_t)(quad & 1) * 2048 + (uint32_t)(quad >> 1) * 128 + l8 * 16;
    const uint32_t boff = (uint32_t)(quad >> 1) * 2048 + (uint32_t)(quad & 1) * 128 + l8 * 16;

#pragma unroll
    for (int ks = 0; ks < 8; ks++) {
        uint32_t ah[4][4], bh[2][4];
#pragma unroll
        for (int f = 0; f < 4; f++)
            ldsm4(ah[f], sb + (uint32_t)(wm * 8 + f * 2) * 2048 + ks * 256 + aoff);
#pragma unroll
        for (int p = 0; p < 2; p++)
            ldsm4(bh[p], sb + 32768 + (uint32_t)(wn * 4 + p * 2) * 2048 + ks * 256 + boff);
#pragma unroll
        for (int f = 0; f < 4; f++)
#pragma unroll
            for (int nf = 0; nf < 4; nf++) {
                int p = nf >> 1, q = (nf & 1) * 2;
                mma_f16(acc[f][nf], ah[f], bh[p][q], bh[p][q + 1]);
            }
    }

    const int rsub = lane >> 2;
    const int csub = (lane & 3) * 2;
    const bool diag = (by == bx);

    float rs[4][2];
    float colp[4][2];
#pragma unroll
    for (int f = 0; f < 4; f++) { rs[f][0] = 0.f; rs[f][1] = 0.f; }
#pragma unroll
    for (int nf = 0; nf < 4; nf++) { colp[nf][0] = 0.f; colp[nf][1] = 0.f; }

#pragma unroll
    for (int f = 0; f < 4; f++) {
#pragma unroll
        for (int nf = 0; nf < 4; nf++) {
            float e00 = ex2f(fmaf(acc[f][nf][0], C_EX2, -C_EX2));
            float e01 = ex2f(fmaf(acc[f][nf][1], C_EX2, -C_EX2));
            float e10 = ex2f(fmaf(acc[f][nf][2], C_EX2, -C_EX2));
            float e11 = ex2f(fmaf(acc[f][nf][3], C_EX2, -C_EX2));
            if (diag) {
                int lr = wm * 64 + f * 16 + rsub;
                int lc = wn * 32 + nf * 8 + csub;
                if (lr == lc)         e00 = 0.f;
                if (lr == lc + 1)     e01 = 0.f;
                if (lr + 8 == lc)     e10 = 0.f;
                if (lr + 8 == lc + 1) e11 = 0.f;
            }
            rs[f][0] += e00 + e01;
            rs[f][1] += e10 + e11;
            colp[nf][0] += e00 + e10;
            colp[nf][1] += e01 + e11;
        }
    }

#pragma unroll
    for (int f = 0; f < 4; f++) {
#pragma unroll
        for (int h = 0; h < 2; h++) {
            float v = rs[f][h];
            v += __shfl_xor_sync(0xffffffffu, v, 1);
            v += __shfl_xor_sync(0xffffffffu, v, 2);
            if ((lane & 3) == 0)
                lsum4[wn * 128 + wm * 64 + f * 16 + h * 8 + rsub] = v;
        }
    }
#pragma unroll
    for (int nf = 0; nf < 4; nf++) {
#pragma unroll
        for (int h = 0; h < 2; h++) {
            float v = colp[nf][h];
            v += __shfl_xor_sync(0xffffffffu, v, 4);
            v += __shfl_xor_sync(0xffffffffu, v, 8);
            v += __shfl_xor_sync(0xffffffffu, v, 16);
            if (lane < 4)
                colarr[wm * 128 + wn * 32 + nf * 8 + lane * 2 + h] = v;
        }
    }
    __syncthreads();
    if (tid < 128) {
        float rtot = lsum4[tid] + lsum4[128 + tid] + lsum4[256 + tid] + lsum4[384 + tid];
        ps[(size_t)bx * MB + by * 128 + tid] = rtot;
        if (!diag) {
            float ctot = colarr[tid] + colarr[128 + tid];
            ps[(size_t)by * MB + bx * 128 + tid] = ctot;
        }
    }
}

// ---------------------------------------------------------------------------
__global__ void sumps_k(const float* __restrict__ ps, float* __restrict__ lse)
{
    const int row = blockIdx.x * 256 + threadIdx.x;
    float tot = 0.f;
#pragma unroll 8
    for (int c = 0; c < 128; c++) tot += ps[(size_t)c * MB + row];
    lse[row] = logf(tot) + INV_T;
}

__global__ void pos_k(const float* __restrict__ Z, float* __restrict__ pos)
{
    const int row = blockIdx.x;
    const int t = threadIdx.x;
    const int prow = (row + MB / 2) & (MB - 1);
    float s = Z[(size_t)row * FF + t] * Z[(size_t)prow * FF + t];
#pragma unroll
    for (int o = 16; o; o >>= 1) s += __shfl_xor_sync(0xffffffffu, s, o);
    __shared__ float ws[4];
    if ((t & 31) == 0) ws[t >> 5] = s;
    __syncthreads();
    if (t == 0) pos[row] = (ws[0] + ws[1] + ws[2] + ws[3]) * INV_T;
}

__global__ void loss_k(const float* __restrict__ lse, const float* __restrict__ pos,
                       float* __restrict__ out)
{
    __shared__ float sm[256];
    const int t = threadIdx.x;
    float s = 0.f;
    for (int i = t; i < MB; i += 256) s += lse[i] - pos[i];
    sm[t] = s;
    __syncthreads();
    for (int o = 128; o; o >>= 1) {
        if (t < o) sm[t] += sm[t + o];
        __syncthreads();
    }
    if (t == 0) out[0] = sm[0] * (1.0f / MB);
}

// ---------------------------------------------------------------------------
extern "C" void kernel_launch(void* const* d_in, const int* in_sizes, int n_in,
                              void* d_out, int out_size)
{
    const float* features = (const float*)d_in[0];
    const float* w1 = (const float*)d_in[1];
    const float* b1 = (const float*)d_in[2];
    const float* w2 = (const float*)d_in[3];
    const float* b2 = (const float*)d_in[4];
    float* out = (float*)d_out;

    __half *fhi, *w1hi, *w2hi, *hhi, *zhi;
    float *z, *psb, *lseb, *posb;
    cudaGetSymbolAddress((void**)&fhi,  g_fhi);
    cudaGetSymbolAddress((void**)&w1hi, g_w1hi);
    cudaGetSymbolAddress((void**)&w2hi, g_w2hi);
    cudaGetSymbolAddress((void**)&hhi,  g_hhi);
    cudaGetSymbolAddress((void**)&zhi,  g_zhi);
    cudaGetSymbolAddress((void**)&z,    g_z);
    cudaGetSymbolAddress((void**)&psb,  g_ps);
    cudaGetSymbolAddress((void**)&lseb, g_lse);
    cudaGetSymbolAddress((void**)&posb, g_pos);

    const int SM_G1 = 98304 + 512;           // 3 stages x 32KB + bias
    const int SM_G2 = 49152 + 512 + 1024;    // 4 stages x 12KB + bias + rowsq
    const int SM_L  = 65536 + 1024 + 2048;   // A + B + colarr + lsum
    cudaFuncSetAttribute(hgemm1_k, cudaFuncAttributeMaxDynamicSharedMemorySize, SM_G1);
    cudaFuncSetAttribute(hgemm2_k, cudaFuncAttributeMaxDynamicSharedMemorySize, SM_G2);
    cudaFuncSetAttribute(lse_tri_k, cudaFuncAttributeMaxDynamicSharedMemorySize, SM_L);

    // prep
    cvt_k<<<1024, 256>>>(features, fhi, (size_t)MB * DD);
    tprep_k<<<dim3(64 + FF / 32, KK / 32), dim3(32, 8)>>>(w1, w2, w1hi, w2hi);

    // 1) h = relu(features @ w1 + b1)
    hgemm1_k<<<dim3(HH / 128, MB / 128), 256, SM_G1>>>(fhi, w1hi, b1, HH, hhi);

    // 2) p = h @ w2 + b2, fused L2-normalize
    float* outz = (out_size >= 1 + MB * FF) ? (out + 1) : nullptr;
    hgemm2_k<<<dim3(1, MB / 64), 256, SM_G2>>>(hhi, w2hi, b2, z, zhi, outz);

    // 3) pos
    pos_k<<<MB, 128>>>(z, posb);

    // 4) triangular masked exp-sum tiles
    const int NTRI = (MB / 128) * (MB / 128 + 1) / 2;   // 8256
    lse_tri_k<<<NTRI, 256, SM_L>>>(zhi, psb);

    // 5) combine partials -> lse, 6) loss
    sumps_k<<<MB / 256, 256>>>(psb, lseb);
    loss_k<<<1, 256>>>(lseb, posb, out);
}